// round 6
// baseline (speedup 1.0000x reference)
#include <cuda_runtime.h>
#include <cuda_fp16.h>
#include <cstdint>

#define N_PIX   16384
#define N_CODES 16384
#define DIM     256
#define HW      1024

#define PX_CTA  64
#define NTILE   256
#define NTILES  (N_CODES / NTILE)   // 64
#define KC      64
#define NCH     (DIM / KC)          // 4
#define NCHUNKS (NTILES * NCH)      // 256
#define GT      128                 // 4 warps, each warp tile 64x64

#define ASTR    264                 // A smem row stride (f16)
#define BSTR    72                  // B smem row stride (f16)
#define A_BYTES      (PX_CTA * ASTR * 2)   // 33792
#define BSTAGE_BYTES (NTILE * BSTR * 2)    // 36864
#define NS_OFF  (A_BYTES + 2 * BSTAGE_BYTES)
#define DYN_BYTES (NS_OFF + 2 * NTILE * 4) // 109568

#define ZQ_ELEMS (16 * DIM * HW)
#define LOSS_OFF ZQ_ELEMS
#define IDX_OFF  (ZQ_ELEMS + 1)

__device__ __half g_Zh[(size_t)N_PIX * DIM];
__device__ __half g_Eh[(size_t)N_CODES * DIM];
__device__ float  g_Zte[(size_t)N_PIX * DIM];
__device__ float  g_norm2[N_CODES];
__device__ int2   g_top2[N_PIX];

__device__ __forceinline__ uint32_t s2u(const void* p) {
    return (uint32_t)__cvta_generic_to_shared(p);
}
__device__ __forceinline__ void cpasync16(uint32_t dst, const void* src) {
    asm volatile("cp.async.cg.shared.global [%0], [%1], 16;" :: "r"(dst), "l"(src));
}
__device__ __forceinline__ void ldsm4(uint32_t* r, uint32_t addr) {
    asm volatile("ldmatrix.sync.aligned.m8n8.x4.shared.b16 {%0,%1,%2,%3}, [%4];"
                 : "=r"(r[0]), "=r"(r[1]), "=r"(r[2]), "=r"(r[3]) : "r"(addr));
}
__device__ __forceinline__ void mma_f16(float* c, const uint32_t* a,
                                        const uint32_t* b) {
    asm volatile(
        "mma.sync.aligned.m16n8k16.row.col.f32.f16.f16.f32 "
        "{%0,%1,%2,%3},{%4,%5,%6,%7},{%8,%9},{%0,%1,%2,%3};"
        : "+f"(c[0]), "+f"(c[1]), "+f"(c[2]), "+f"(c[3])
        : "r"(a[0]), "r"(a[1]), "r"(a[2]), "r"(a[3]), "r"(b[0]), "r"(b[1]));
}

// ---------------------------------------------------------------------------
// Merged prep: blocks [0,512) transpose+convert z; blocks [512,2560) do E.
// ---------------------------------------------------------------------------
__global__ void __launch_bounds__(256)
prep_kernel(const float* __restrict__ z, const float* __restrict__ emb) {
    const int tid = threadIdx.x, lane = tid & 31, wid = tid >> 5;
    if (blockIdx.x < 512) {
        __shared__ float Zs[DIM][33];
        int px0 = blockIdx.x * 32;
        int b = px0 >> 10, hw0 = px0 & (HW - 1);
        for (int i = tid; i < DIM * 32; i += 256) {
            int d = i >> 5, px = i & 31;
            Zs[d][px] = z[((size_t)b * DIM + d) * HW + hw0 + px];
        }
        __syncthreads();
#pragma unroll
        for (int pp = 0; pp < 4; pp++) {
            int px = wid + pp * 8;
            __half* rowH = g_Zh + (size_t)(px0 + px) * DIM;
            float* rowE = g_Zte + (size_t)(px0 + px) * DIM;
#pragma unroll
            for (int i = 0; i < 8; i++) {
                int d = lane + 32 * i;
                float v = Zs[d][px];
                rowH[d] = __float2half_rn(v);
                rowE[d] = v;
            }
        }
    } else {
        int code = (blockIdx.x - 512) * 8 + wid;
        const float* src = emb + (size_t)code * DIM + lane * 8;
        __half* row = g_Eh + (size_t)code * DIM;
        float en = 0.f;
#pragma unroll
        for (int t = 0; t < 8; t++) {
            float v = src[t];
            en += v * v;
            row[lane * 8 + t] = __float2half_rn(v);
        }
#pragma unroll
        for (int o = 16; o > 0; o >>= 1) en += __shfl_xor_sync(0xffffffffu, en, o);
        if (lane == 0) g_norm2[code] = en;
    }
}

// ---------------------------------------------------------------------------
// Main GEMM: 4 warps, warp tile 64x64 (all 64 px x 64 codes), CTA N tile 256.
// ---------------------------------------------------------------------------
__global__ void __launch_bounds__(GT, 2)
vq_gemm_kernel() {
    extern __shared__ char dsm[];
    __half* As = (__half*)dsm;
    char* Bs = dsm + A_BYTES;
    float* Ns = (float*)(dsm + NS_OFF);

    const int tid = threadIdx.x;
    const int lane = tid & 31;
    const int nw = tid >> 5;          // warp = N slice (0..3)
    const int g = lane >> 2;
    const int tig = lane & 3;
    const int p0 = blockIdx.x * PX_CTA;

    // ---- prologue: A panel (64 x 256 f16): 2 threads per row ----
    {
        int r = tid >> 1, q = tid & 1;
        const __half* src = g_Zh + (size_t)(p0 + r) * DIM + q * 128;
        uint32_t dst = s2u(As + r * ASTR + q * 128);
#pragma unroll
        for (int j = 0; j < 16; j++) cpasync16(dst + j * 16, src + j * 8);
    }
    // ---- chunk 0 (tile 0, k0) + norms tile 0 ----
    {
#pragma unroll
        for (int j = 0; j < 2; j++) {
            int row = tid * 2 + j;
            const __half* src = g_Eh + (size_t)row * DIM;
            uint32_t dst = s2u(Bs + row * (BSTR * 2));
#pragma unroll
            for (int q = 0; q < 8; q++) cpasync16(dst + q * 16, src + q * 8);
        }
        if (tid < 64) cpasync16(s2u(Ns + tid * 4), g_norm2 + tid * 4);
    }
    asm volatile("cp.async.commit_group;" ::: "memory");

    float acc[4][8][4];
#pragma unroll
    for (int mt = 0; mt < 4; mt++)
#pragma unroll
        for (int nt = 0; nt < 8; nt++)
#pragma unroll
            for (int r = 0; r < 4; r++) acc[mt][nt][r] = 0.f;

    float v1[8], v2[8];
    int i1[8], i2[8];
#pragma unroll
    for (int s = 0; s < 8; s++) { v1[s] = v2[s] = -3.4e38f; i1[s] = 0; i2[s] = 1; }

    const int a_row_l = (lane & 7) + ((lane >> 3) & 1) * 8;
    const int a_col_l = (lane >> 4) * 8;
    const int b_row_l = ((lane >> 4) & 1) * 8 + (lane & 7);
    const int b_col_l = ((lane >> 3) & 1) * 8;

    for (int cc = 0; cc < NCHUNKS; cc++) {
        asm volatile("cp.async.wait_group 0;" ::: "memory");
        __syncthreads();

        // issue chunk cc+1 into the other stage
        if (cc + 1 < NCHUNKS) {
            const int nx = cc + 1;
            const int tn = nx >> 2, kn = nx & 3;
            uint32_t dstb = s2u(Bs + (nx & 1) * BSTAGE_BYTES);
#pragma unroll
            for (int j = 0; j < 2; j++) {
                int row = tid * 2 + j;
                const __half* src =
                    g_Eh + (size_t)(tn * NTILE + row) * DIM + kn * KC;
                uint32_t dst = dstb + row * (BSTR * 2);
#pragma unroll
                for (int q = 0; q < 8; q++) cpasync16(dst + q * 16, src + q * 8);
            }
            if (kn == 0 && tid < 64)
                cpasync16(s2u(Ns + (tn & 1) * NTILE + tid * 4),
                          g_norm2 + (size_t)tn * NTILE + tid * 4);
        }
        asm volatile("cp.async.commit_group;" ::: "memory");

        // compute chunk cc: 4 k16-steps; A k-offset = (cc&3)*KC
        const char* sb = Bs + (cc & 1) * BSTAGE_BYTES;
        const int kb0 = (cc & 3) * KC;
#pragma unroll
        for (int s = 0; s < 4; s++) {
            uint32_t a[4][4];
#pragma unroll
            for (int mt = 0; mt < 4; mt++) {
                uint32_t addr = s2u(As + (mt * 16 + a_row_l) * ASTR +
                                    kb0 + s * 16 + a_col_l);
                ldsm4(a[mt], addr);
            }
            uint32_t b[8][2];
#pragma unroll
            for (int np = 0; np < 4; np++) {
                uint32_t r[4];
                uint32_t addr = s2u(sb + (nw * 64 + np * 16 + b_row_l) *
                                    (BSTR * 2) + (s * 16 + b_col_l) * 2);
                ldsm4(r, addr);
                b[2 * np][0] = r[0]; b[2 * np][1] = r[1];
                b[2 * np + 1][0] = r[2]; b[2 * np + 1][1] = r[3];
            }
#pragma unroll
            for (int mt = 0; mt < 4; mt++)
#pragma unroll
                for (int nt = 0; nt < 8; nt++)
                    mma_f16(acc[mt][nt], a[mt], b[nt]);
        }

        // fold tile every 4 chunks
        if ((cc & 3) == 3) {
            const int t = cc >> 2;
            const float2* nsp = (const float2*)(Ns + (t & 1) * NTILE);
#pragma unroll
            for (int nt = 0; nt < 8; nt++) {
                float2 nn = nsp[nw * 32 + nt * 4 + tig];
                const int c0 = t * NTILE + nw * 64 + nt * 8 + 2 * tig;
#pragma unroll
                for (int mt = 0; mt < 4; mt++) {
                    float s0 = acc[mt][nt][0] - 0.5f * nn.x;
                    float s1 = acc[mt][nt][1] - 0.5f * nn.y;
                    float s2 = acc[mt][nt][2] - 0.5f * nn.x;
                    float s3 = acc[mt][nt][3] - 0.5f * nn.y;
                    const int sa = mt * 2, sb2 = mt * 2 + 1;
                    if (s0 > v1[sa]) { v2[sa]=v1[sa]; i2[sa]=i1[sa]; v1[sa]=s0; i1[sa]=c0; }
                    else if (s0 > v2[sa]) { v2[sa]=s0; i2[sa]=c0; }
                    if (s1 > v1[sa]) { v2[sa]=v1[sa]; i2[sa]=i1[sa]; v1[sa]=s1; i1[sa]=c0+1; }
                    else if (s1 > v2[sa]) { v2[sa]=s1; i2[sa]=c0+1; }
                    if (s2 > v1[sb2]) { v2[sb2]=v1[sb2]; i2[sb2]=i1[sb2]; v1[sb2]=s2; i1[sb2]=c0; }
                    else if (s2 > v2[sb2]) { v2[sb2]=s2; i2[sb2]=c0; }
                    if (s3 > v1[sb2]) { v2[sb2]=v1[sb2]; i2[sb2]=i1[sb2]; v1[sb2]=s3; i1[sb2]=c0+1; }
                    else if (s3 > v2[sb2]) { v2[sb2]=s3; i2[sb2]=c0+1; }
                    acc[mt][nt][0] = acc[mt][nt][1] = 0.f;
                    acc[mt][nt][2] = acc[mt][nt][3] = 0.f;
                }
            }
        }
    }

    // ---- cross-thread top-2 reduce ----
    __syncthreads();
    float4* red = (float4*)dsm;   // [64 px][16 contributors]
#pragma unroll
    for (int s = 0; s < 8; s++) {
        int mt = s >> 1, h = s & 1;
        int pxl = mt * 16 + h * 8 + g;
        red[pxl * 16 + nw * 4 + tig] =
            make_float4(v1[s], __int_as_float(i1[s]),
                        v2[s], __int_as_float(i2[s]));
    }
    __syncthreads();
    if (tid < PX_CTA) {
        float bv1 = -3.4e38f, bv2 = -3.4e38f;
        int bi1 = 0, bi2 = 1;
#pragma unroll
        for (int c = 0; c < 16; c++) {
            float4 e = red[tid * 16 + c];
#pragma unroll
            for (int h = 0; h < 2; h++) {
                float v = h ? e.z : e.x;
                int idx = __float_as_int(h ? e.w : e.y);
                if (v > bv1 || (v == bv1 && idx < bi1)) {
                    bv2 = bv1; bi2 = bi1; bv1 = v; bi1 = idx;
                } else if (v > bv2) { bv2 = v; bi2 = idx; }
            }
        }
        g_top2[p0 + tid] = make_int2(bi1, bi2);
    }
}

// ---------------------------------------------------------------------------
__global__ void __launch_bounds__(256)
rescore_gather_kernel(const float* __restrict__ emb, float* __restrict__ out) {
    __shared__ int sel[PX_CTA];
    const int tid = threadIdx.x, lane = tid & 31, wid = tid >> 5;
    const int p0 = blockIdx.x * PX_CTA;

#pragma unroll 1
    for (int j = 0; j < 8; j++) {
        const int pxl = wid * 8 + j;
        const int px = p0 + pxl;
        const int2 cand = g_top2[px];
        const float4* zp = (const float4*)(g_Zte + (size_t)px * DIM);
        const float4* e1 = (const float4*)(emb + (size_t)cand.x * DIM);
        const float4* e2 = (const float4*)(emb + (size_t)cand.y * DIM);
        float d1 = 0.f, d2 = 0.f;
#pragma unroll
        for (int t = 0; t < 2; t++) {
            float4 zv = zp[lane + 32 * t];
            float4 a = e1[lane + 32 * t];
            float4 b = e2[lane + 32 * t];
            d1 += zv.x * a.x + zv.y * a.y + zv.z * a.z + zv.w * a.w;
            d2 += zv.x * b.x + zv.y * b.y + zv.z * b.z + zv.w * b.w;
        }
#pragma unroll
        for (int o = 16; o > 0; o >>= 1) {
            d1 += __shfl_xor_sync(0xffffffffu, d1, o);
            d2 += __shfl_xor_sync(0xffffffffu, d2, o);
        }
        if (lane == 0) {
            float s1 = d1 - 0.5f * g_norm2[cand.x];
            float s2 = d2 - 0.5f * g_norm2[cand.y];
            int best;
            if (s1 > s2) best = cand.x;
            else if (s2 > s1) best = cand.y;
            else best = min(cand.x, cand.y);
            sel[pxl] = best;
            out[IDX_OFF + px] = (float)best;
        }
    }
    __syncthreads();

    const int b = p0 >> 10;
    const int hw0 = p0 & (HW - 1);
    for (int i = tid; i < DIM * PX_CTA; i += 256) {
        int d = i >> 6, pxl = i & 63;
        out[((size_t)b * DIM + d) * HW + hw0 + pxl] =
            emb[(size_t)sel[pxl] * DIM + d];
    }
    if (blockIdx.x == 0 && tid == 0) out[LOSS_OFF] = 0.f;
}

// ---------------------------------------------------------------------------
extern "C" void kernel_launch(void* const* d_in, const int* in_sizes, int n_in,
                              void* d_out, int out_size) {
    const float* z = (const float*)d_in[0];
    const float* emb = (const float*)d_in[1];
    float* out = (float*)d_out;
    (void)in_sizes; (void)n_in; (void)out_size;

    static bool attr_set = false;
    if (!attr_set) {
        cudaFuncSetAttribute(vq_gemm_kernel,
                             cudaFuncAttributeMaxDynamicSharedMemorySize,
                             DYN_BYTES);
        attr_set = true;
    }

    prep_kernel<<<2560, 256>>>(z, emb);
    vq_gemm_kernel<<<N_PIX / PX_CTA, GT, DYN_BYTES>>>();
    rescore_gather_kernel<<<N_PIX / PX_CTA, 256>>>(emb, out);
}

// round 7
// speedup vs baseline: 1.1468x; 1.1468x over previous
#include <cuda_runtime.h>
#include <cuda_fp16.h>
#include <cstdint>

#define N_PIX   16384
#define N_CODES 16384
#define DIM     256
#define HW      1024

#define PX_CTA  64
#define NTILE   256
#define NTILES  (N_CODES / NTILE)   // 64
#define KC      32
#define NCH     (DIM / KC)          // 8 chunks per tile
#define NCHUNKS (NTILES * NCH)      // 512
#define NSTAGE  3
#define GT      256                 // 8 warps: 2M x 4N, warp tile 32x64

#define ASTR    264                 // A smem row stride (f16): 528B, ldsm-safe
#define BSTR    40                  // B smem row stride (f16): 80B, ldsm-safe
#define A_BYTES      (PX_CTA * ASTR * 2)   // 33792
#define BSTAGE_BYTES (NTILE * BSTR * 2)    // 20480
#define NS_OFF  (A_BYTES + NSTAGE * BSTAGE_BYTES)
#define DYN_BYTES (NS_OFF + 2 * NTILE * 4) // 97280

#define ZQ_ELEMS (16 * DIM * HW)
#define LOSS_OFF ZQ_ELEMS
#define IDX_OFF  (ZQ_ELEMS + 1)

__device__ __half g_Zh[(size_t)N_PIX * DIM];
__device__ __half g_Eh[(size_t)N_CODES * DIM];
__device__ float  g_Zte[(size_t)N_PIX * DIM];
__device__ float  g_norm2[N_CODES];

__device__ __forceinline__ uint32_t s2u(const void* p) {
    return (uint32_t)__cvta_generic_to_shared(p);
}
__device__ __forceinline__ void cpasync16(uint32_t dst, const void* src) {
    asm volatile("cp.async.cg.shared.global [%0], [%1], 16;" :: "r"(dst), "l"(src));
}
__device__ __forceinline__ void ldsm4(uint32_t* r, uint32_t addr) {
    asm volatile("ldmatrix.sync.aligned.m8n8.x4.shared.b16 {%0,%1,%2,%3}, [%4];"
                 : "=r"(r[0]), "=r"(r[1]), "=r"(r[2]), "=r"(r[3]) : "r"(addr));
}
__device__ __forceinline__ void mma_f16(float* c, const uint32_t* a,
                                        const uint32_t* b) {
    asm volatile(
        "mma.sync.aligned.m16n8k16.row.col.f32.f16.f16.f32 "
        "{%0,%1,%2,%3},{%4,%5,%6,%7},{%8,%9},{%0,%1,%2,%3};"
        : "+f"(c[0]), "+f"(c[1]), "+f"(c[2]), "+f"(c[3])
        : "r"(a[0]), "r"(a[1]), "r"(a[2]), "r"(a[3]), "r"(b[0]), "r"(b[1]));
}

// ---------------------------------------------------------------------------
// Merged prep: blocks [0,512) transpose+convert z; blocks [512,2560) do E.
// ---------------------------------------------------------------------------
__global__ void __launch_bounds__(256)
prep_kernel(const float* __restrict__ z, const float* __restrict__ emb) {
    const int tid = threadIdx.x, lane = tid & 31, wid = tid >> 5;
    if (blockIdx.x < 512) {
        __shared__ float Zs[DIM][33];
        int px0 = blockIdx.x * 32;
        int b = px0 >> 10, hw0 = px0 & (HW - 1);
        for (int i = tid; i < DIM * 32; i += 256) {
            int d = i >> 5, px = i & 31;
            Zs[d][px] = z[((size_t)b * DIM + d) * HW + hw0 + px];
        }
        __syncthreads();
#pragma unroll
        for (int pp = 0; pp < 4; pp++) {
            int px = wid + pp * 8;
            __half* rowH = g_Zh + (size_t)(px0 + px) * DIM;
            float* rowE = g_Zte + (size_t)(px0 + px) * DIM;
#pragma unroll
            for (int i = 0; i < 8; i++) {
                int d = lane + 32 * i;
                float v = Zs[d][px];
                rowH[d] = __float2half_rn(v);
                rowE[d] = v;
            }
        }
    } else {
        int code = (blockIdx.x - 512) * 8 + wid;
        const float* src = emb + (size_t)code * DIM + lane * 8;
        __half* row = g_Eh + (size_t)code * DIM;
        float en = 0.f;
#pragma unroll
        for (int t = 0; t < 8; t++) {
            float v = src[t];
            en += v * v;
            row[lane * 8 + t] = __float2half_rn(v);
        }
#pragma unroll
        for (int o = 16; o > 0; o >>= 1) en += __shfl_xor_sync(0xffffffffu, en, o);
        if (lane == 0) g_norm2[code] = en;
    }
}

// ---------------------------------------------------------------------------
// B chunk loader: 256 rows x 32 f16 (64B), one row per thread, 4x16B.
// ---------------------------------------------------------------------------
__device__ __forceinline__ void load_b_chunk(uint32_t dstb, int tn, int kn,
                                             int tid) {
    const __half* src = g_Eh + (size_t)(tn * NTILE + tid) * DIM + kn * KC;
    uint32_t dst = dstb + tid * (BSTR * 2);
#pragma unroll
    for (int q = 0; q < 4; q++) cpasync16(dst + q * 16, src + q * 8);
}

// ---------------------------------------------------------------------------
// Main: fused GEMM + int-packed top-2 + exact rescore + gather.
// ---------------------------------------------------------------------------
__global__ void __launch_bounds__(GT, 2)
vq_gemm_kernel(const float* __restrict__ emb, float* __restrict__ out) {
    extern __shared__ char dsm[];
    __half* As = (__half*)dsm;
    char* Bs = dsm + A_BYTES;
    float* Ns = (float*)(dsm + NS_OFF);
    __shared__ int2 s_cand[PX_CTA];
    __shared__ int s_sel[PX_CTA];

    const int tid = threadIdx.x;
    const int lane = tid & 31;
    const int wid = tid >> 5;
    const int mw = wid >> 2;          // 0..1
    const int nw = wid & 3;           // 0..3
    const int g = lane >> 2;
    const int tig = lane & 3;
    const int p0 = blockIdx.x * PX_CTA;

    // ---- prologue: A panel + chunk0 + norms0 (group 0), chunk1 (group 1) ----
    {
        int r = tid >> 2, q = tid & 3;
        const __half* src = g_Zh + (size_t)(p0 + r) * DIM + q * 64;
        uint32_t dst = s2u(As + r * ASTR + q * 64);
#pragma unroll
        for (int j = 0; j < 8; j++) cpasync16(dst + j * 16, src + j * 8);
    }
    load_b_chunk(s2u(Bs), 0, 0, tid);
    if (tid < 64) cpasync16(s2u(Ns + tid * 4), g_norm2 + tid * 4);
    asm volatile("cp.async.commit_group;" ::: "memory");
    load_b_chunk(s2u(Bs + BSTAGE_BYTES), 0, 1, tid);
    asm volatile("cp.async.commit_group;" ::: "memory");

    float acc[2][8][4];
#pragma unroll
    for (int mt = 0; mt < 2; mt++)
#pragma unroll
        for (int nt = 0; nt < 8; nt++)
#pragma unroll
            for (int r = 0; r < 4; r++) acc[mt][nt][r] = 0.f;

    int v1[4], v2[4];
#pragma unroll
    for (int s = 0; s < 4; s++) { v1[s] = INT_MIN; v2[s] = INT_MIN; }

    const int a_row_l = (lane & 7) + ((lane >> 3) & 1) * 8;
    const int a_col_l = (lane >> 4) * 8;
    const int b_row_l = ((lane >> 4) & 1) * 8 + (lane & 7);
    const int b_col_l = ((lane >> 3) & 1) * 8;

    for (int cc = 0; cc < NCHUNKS; cc++) {
        asm volatile("cp.async.wait_group 1;" ::: "memory");
        __syncthreads();

        // issue chunk cc+2 (buffer of chunk cc-1, freed by the sync above)
        if (cc + 2 < NCHUNKS) {
            const int nx = cc + 2;
            const int tn = nx >> 3, kn = nx & 7;
            int stage = nx % NSTAGE;
            load_b_chunk(s2u(Bs + stage * BSTAGE_BYTES), tn, kn, tid);
            if (kn == 0 && tid < 64)
                cpasync16(s2u(Ns + (tn & 1) * NTILE + tid * 4),
                          g_norm2 + (size_t)tn * NTILE + tid * 4);
        }
        asm volatile("cp.async.commit_group;" ::: "memory");

        // compute chunk cc: 2 k16-steps
        const char* sb = Bs + (cc % NSTAGE) * BSTAGE_BYTES;
        const int kb0 = (cc & 7) * KC;
#pragma unroll
        for (int s = 0; s < 2; s++) {
            uint32_t a[2][4];
#pragma unroll
            for (int mt = 0; mt < 2; mt++) {
                uint32_t addr = s2u(As + (mw * 32 + mt * 16 + a_row_l) * ASTR +
                                    kb0 + s * 16 + a_col_l);
                ldsm4(a[mt], addr);
            }
            uint32_t b[8][2];
#pragma unroll
            for (int np = 0; np < 4; np++) {
                uint32_t r[4];
                uint32_t addr = s2u(sb + (nw * 64 + np * 16 + b_row_l) *
                                    (BSTR * 2) + (s * 16 + b_col_l) * 2);
                ldsm4(r, addr);
                b[2 * np][0] = r[0]; b[2 * np][1] = r[1];
                b[2 * np + 1][0] = r[2]; b[2 * np + 1][1] = r[3];
            }
#pragma unroll
            for (int mt = 0; mt < 2; mt++)
#pragma unroll
                for (int nt = 0; nt < 8; nt++)
                    mma_f16(acc[mt][nt], a[mt], b[nt]);
        }

        // fold tile every 8 chunks: branch-free int-packed top-2
        if ((cc & 7) == 7) {
            const int t = cc >> 3;
            const float2* nsp = (const float2*)(Ns + (t & 1) * NTILE);
#pragma unroll
            for (int nt = 0; nt < 8; nt++) {
                float2 nn = nsp[nw * 32 + nt * 4 + tig];
                const int c0 = t * NTILE + nw * 64 + nt * 8 + 2 * tig;
#pragma unroll
                for (int mt = 0; mt < 2; mt++) {
#pragma unroll
                    for (int r = 0; r < 4; r++) {
                        float nrm = (r & 1) ? nn.y : nn.x;
                        float sv = fmaf(nrm, -0.5f, acc[mt][nt][r]);
                        int key = __float2int_rn(sv * 128.0f) * 16384 +
                                  (c0 + (r & 1));
                        const int sl = mt * 2 + (r >> 1);
                        int nv1 = max(v1[sl], key);
                        v2[sl] = max(v2[sl], min(v1[sl], key));
                        v1[sl] = nv1;
                        acc[mt][nt][r] = 0.f;
                    }
                }
            }
        }
    }

    // ---- cross-thread top-2 reduce (16 contributors per pixel) ----
    __syncthreads();
    int2* red = (int2*)dsm;       // [64 px][16]
#pragma unroll
    for (int s = 0; s < 4; s++) {
        int pxl = mw * 32 + (s >> 1) * 16 + (s & 1) * 8 + g;
        red[pxl * 16 + nw * 4 + tig] = make_int2(v1[s], v2[s]);
    }
    __syncthreads();
    if (tid < PX_CTA) {
        int bv1 = INT_MIN, bv2 = INT_MIN;
#pragma unroll
        for (int c = 0; c < 16; c++) {
            int2 e = red[tid * 16 + c];
            int nv1 = max(bv1, e.x);
            bv2 = max(bv2, min(bv1, e.x));
            bv1 = nv1;
            nv1 = max(bv1, e.y);
            bv2 = max(bv2, min(bv1, e.y));
            bv1 = nv1;
        }
        s_cand[tid] = make_int2(bv1 & 16383, bv2 & 16383);
    }
    __syncthreads();

    // ---- exact fp32 rescore of the 2 candidates per pixel ----
#pragma unroll 1
    for (int j = 0; j < 8; j++) {
        const int pxl = wid * 8 + j;
        const int px = p0 + pxl;
        const int2 cand = s_cand[pxl];
        const float4* zp = (const float4*)(g_Zte + (size_t)px * DIM);
        const float4* e1 = (const float4*)(emb + (size_t)cand.x * DIM);
        const float4* e2 = (const float4*)(emb + (size_t)cand.y * DIM);
        float d1 = 0.f, d2 = 0.f;
#pragma unroll
        for (int t = 0; t < 2; t++) {
            float4 zv = zp[lane + 32 * t];
            float4 a = e1[lane + 32 * t];
            float4 b = e2[lane + 32 * t];
            d1 += zv.x * a.x + zv.y * a.y + zv.z * a.z + zv.w * a.w;
            d2 += zv.x * b.x + zv.y * b.y + zv.z * b.z + zv.w * b.w;
        }
#pragma unroll
        for (int o = 16; o > 0; o >>= 1) {
            d1 += __shfl_xor_sync(0xffffffffu, d1, o);
            d2 += __shfl_xor_sync(0xffffffffu, d2, o);
        }
        if (lane == 0) {
            float s1 = d1 - 0.5f * g_norm2[cand.x];
            float s2 = d2 - 0.5f * g_norm2[cand.y];
            int best;
            if (s1 > s2) best = cand.x;
            else if (s2 > s1) best = cand.y;
            else best = min(cand.x, cand.y);
            s_sel[pxl] = best;
            out[IDX_OFF + px] = (float)best;
        }
    }
    __syncthreads();

    // ---- gather z_q in NCHW ----
    const int b = p0 >> 10;
    const int hw0 = p0 & (HW - 1);
    for (int i = tid; i < DIM * PX_CTA; i += GT) {
        int d = i >> 6, pxl = i & 63;
        out[((size_t)b * DIM + d) * HW + hw0 + pxl] =
            emb[(size_t)s_sel[pxl] * DIM + d];
    }
    if (blockIdx.x == 0 && tid == 0) out[LOSS_OFF] = 0.f;
}

// ---------------------------------------------------------------------------
extern "C" void kernel_launch(void* const* d_in, const int* in_sizes, int n_in,
                              void* d_out, int out_size) {
    const float* z = (const float*)d_in[0];
    const float* emb = (const float*)d_in[1];
    float* out = (float*)d_out;
    (void)in_sizes; (void)n_in; (void)out_size;

    static bool attr_set = false;
    if (!attr_set) {
        cudaFuncSetAttribute(vq_gemm_kernel,
                             cudaFuncAttributeMaxDynamicSharedMemorySize,
                             DYN_BYTES);
        attr_set = true;
    }

    prep_kernel<<<2560, 256>>>(z, emb);
    vq_gemm_kernel<<<N_PIX / PX_CTA, GT, DYN_BYTES>>>(emb, out);
}

// round 8
// speedup vs baseline: 1.5985x; 1.3940x over previous
#include <cuda_runtime.h>
#include <cuda_fp16.h>
#include <cstdint>

#define N_PIX   16384
#define N_CODES 16384
#define DIM     256
#define HW      1024

#define PX_CTA  128
#define NTILE   256
#define NTILES  (N_CODES / NTILE)   // 64
#define KC      64
#define NCH     (DIM / KC)          // 4 chunks per tile
#define NCHUNKS (NTILES * NCH)      // 256
#define NSTAGE  4
#define GT      512                 // 16 warps: 4M x 4N, warp tile 32x64

#define ASTR    264                 // A smem row stride (f16)
#define BSTR    72                  // B smem row stride (f16)
#define A_BYTES      (PX_CTA * ASTR * 2)   // 67584
#define BSTAGE_BYTES (NTILE * BSTR * 2)    // 36864
#define NS_OFF  (A_BYTES + NSTAGE * BSTAGE_BYTES)
#define DYN_BYTES (NS_OFF + 2 * NTILE * 4) // 217088

#define ZQ_ELEMS (16 * DIM * HW)
#define LOSS_OFF ZQ_ELEMS
#define IDX_OFF  (ZQ_ELEMS + 1)

__device__ __half g_Zh[(size_t)N_PIX * DIM];
__device__ __half g_Eh[(size_t)N_CODES * DIM];
__device__ float  g_Zte[(size_t)N_PIX * DIM];
__device__ float  g_norm2[N_CODES];

__device__ __forceinline__ uint32_t s2u(const void* p) {
    return (uint32_t)__cvta_generic_to_shared(p);
}
__device__ __forceinline__ void cpasync16(uint32_t dst, const void* src) {
    asm volatile("cp.async.cg.shared.global [%0], [%1], 16;" :: "r"(dst), "l"(src));
}
__device__ __forceinline__ void ldsm4(uint32_t* r, uint32_t addr) {
    asm volatile("ldmatrix.sync.aligned.m8n8.x4.shared.b16 {%0,%1,%2,%3}, [%4];"
                 : "=r"(r[0]), "=r"(r[1]), "=r"(r[2]), "=r"(r[3]) : "r"(addr));
}
__device__ __forceinline__ void mma_f16(float* c, const uint32_t* a,
                                        const uint32_t* b) {
    asm volatile(
        "mma.sync.aligned.m16n8k16.row.col.f32.f16.f16.f32 "
        "{%0,%1,%2,%3},{%4,%5,%6,%7},{%8,%9},{%0,%1,%2,%3};"
        : "+f"(c[0]), "+f"(c[1]), "+f"(c[2]), "+f"(c[3])
        : "r"(a[0]), "r"(a[1]), "r"(a[2]), "r"(a[3]), "r"(b[0]), "r"(b[1]));
}

// ---------------------------------------------------------------------------
// Merged prep: blocks [0,512) transpose+convert z; blocks [512,2560) do E.
// ---------------------------------------------------------------------------
__global__ void __launch_bounds__(256)
prep_kernel(const float* __restrict__ z, const float* __restrict__ emb) {
    const int tid = threadIdx.x, lane = tid & 31, wid = tid >> 5;
    if (blockIdx.x < 512) {
        __shared__ float Zs[DIM][33];
        int px0 = blockIdx.x * 32;
        int b = px0 >> 10, hw0 = px0 & (HW - 1);
        for (int i = tid; i < DIM * 32; i += 256) {
            int d = i >> 5, px = i & 31;
            Zs[d][px] = z[((size_t)b * DIM + d) * HW + hw0 + px];
        }
        __syncthreads();
#pragma unroll
        for (int pp = 0; pp < 4; pp++) {
            int px = wid + pp * 8;
            __half* rowH = g_Zh + (size_t)(px0 + px) * DIM;
            float* rowE = g_Zte + (size_t)(px0 + px) * DIM;
#pragma unroll
            for (int i = 0; i < 8; i++) {
                int d = lane + 32 * i;
                float v = Zs[d][px];
                rowH[d] = __float2half_rn(v);
                rowE[d] = v;
            }
        }
    } else {
        int code = (blockIdx.x - 512) * 8 + wid;
        const float* src = emb + (size_t)code * DIM + lane * 8;
        __half* row = g_Eh + (size_t)code * DIM;
        float en = 0.f;
#pragma unroll
        for (int t = 0; t < 8; t++) {
            float v = src[t];
            en += v * v;
            row[lane * 8 + t] = __float2half_rn(v);
        }
#pragma unroll
        for (int o = 16; o > 0; o >>= 1) en += __shfl_xor_sync(0xffffffffu, en, o);
        if (lane == 0) g_norm2[code] = en;
    }
}

// ---------------------------------------------------------------------------
// B chunk loader (512 threads): 256 rows x 64 f16 (128B); 2 threads per row.
// ---------------------------------------------------------------------------
__device__ __forceinline__ void load_b_chunk(uint32_t dstb, int tn, int kn,
                                             int tid) {
    const int row = tid >> 1, half = tid & 1;
    const __half* src =
        g_Eh + (size_t)(tn * NTILE + row) * DIM + kn * KC + half * 32;
    uint32_t dst = dstb + row * (BSTR * 2) + half * 64;
#pragma unroll
    for (int q = 0; q < 4; q++) cpasync16(dst + q * 16, src + q * 8);
}

// ---------------------------------------------------------------------------
// Main: fused GEMM (128px x 16384 codes) + packed top-2 + rescore + gather.
// ---------------------------------------------------------------------------
__global__ void __launch_bounds__(GT, 1)
vq_gemm_kernel(const float* __restrict__ emb, float* __restrict__ out) {
    extern __shared__ char dsm[];
    __half* As = (__half*)dsm;
    char* Bs = dsm + A_BYTES;
    float* Ns = (float*)(dsm + NS_OFF);
    __shared__ int2 s_cand[PX_CTA];
    __shared__ int s_sel[PX_CTA];

    const int tid = threadIdx.x;
    const int lane = tid & 31;
    const int wid = tid >> 5;
    const int mw = wid >> 2;          // 0..3
    const int nw = wid & 3;           // 0..3
    const int g = lane >> 2;
    const int tig = lane & 3;
    const int p0 = blockIdx.x * PX_CTA;

    // ---- prologue: A panel + chunk0 + norms0; then chunks 1,2 ----
    {
        int r = tid >> 2, q = tid & 3;     // 128 rows, 4 threads/row
        const __half* src = g_Zh + (size_t)(p0 + r) * DIM + q * 64;
        uint32_t dst = s2u(As + r * ASTR + q * 64);
#pragma unroll
        for (int j = 0; j < 8; j++) cpasync16(dst + j * 16, src + j * 8);
    }
    load_b_chunk(s2u(Bs), 0, 0, tid);
    if (tid < 64) cpasync16(s2u(Ns + tid * 4), g_norm2 + tid * 4);
    asm volatile("cp.async.commit_group;" ::: "memory");
    load_b_chunk(s2u(Bs + BSTAGE_BYTES), 0, 1, tid);
    asm volatile("cp.async.commit_group;" ::: "memory");
    load_b_chunk(s2u(Bs + 2 * BSTAGE_BYTES), 0, 2, tid);
    asm volatile("cp.async.commit_group;" ::: "memory");

    float acc[2][8][4];
#pragma unroll
    for (int mt = 0; mt < 2; mt++)
#pragma unroll
        for (int nt = 0; nt < 8; nt++)
#pragma unroll
            for (int r = 0; r < 4; r++) acc[mt][nt][r] = 0.f;

    int v1[4], v2[4];
#pragma unroll
    for (int s = 0; s < 4; s++) { v1[s] = INT_MIN; v2[s] = INT_MIN; }

    const int a_row_l = (lane & 7) + ((lane >> 3) & 1) * 8;
    const int a_col_l = (lane >> 4) * 8;
    const int b_row_l = ((lane >> 4) & 1) * 8 + (lane & 7);
    const int b_col_l = ((lane >> 3) & 1) * 8;

    for (int cc = 0; cc < NCHUNKS; cc++) {
        asm volatile("cp.async.wait_group 2;" ::: "memory");
        __syncthreads();

        // issue chunk cc+3 into the stage freed by chunk cc-1
        if (cc + 3 < NCHUNKS) {
            const int nx = cc + 3;
            const int tn = nx >> 2, kn = nx & 3;
            load_b_chunk(s2u(Bs + (nx & 3) * BSTAGE_BYTES), tn, kn, tid);
            if (kn == 0 && tid < 64)
                cpasync16(s2u(Ns + (tn & 1) * NTILE + tid * 4),
                          g_norm2 + (size_t)tn * NTILE + tid * 4);
        }
        asm volatile("cp.async.commit_group;" ::: "memory");

        // compute chunk cc: 4 k16-steps; A k-offset = (cc&3)*KC
        const char* sb = Bs + (cc & 3) * BSTAGE_BYTES;
        const int kb0 = (cc & 3) * KC;
#pragma unroll
        for (int s = 0; s < 4; s++) {
            uint32_t a[2][4];
#pragma unroll
            for (int mt = 0; mt < 2; mt++) {
                uint32_t addr = s2u(As + (mw * 32 + mt * 16 + a_row_l) * ASTR +
                                    kb0 + s * 16 + a_col_l);
                ldsm4(a[mt], addr);
            }
            uint32_t b[8][2];
#pragma unroll
            for (int np = 0; np < 4; np++) {
                uint32_t r[4];
                uint32_t addr = s2u(sb + (nw * 64 + np * 16 + b_row_l) *
                                    (BSTR * 2) + (s * 16 + b_col_l) * 2);
                ldsm4(r, addr);
                b[2 * np][0] = r[0]; b[2 * np][1] = r[1];
                b[2 * np + 1][0] = r[2]; b[2 * np + 1][1] = r[3];
            }
#pragma unroll
            for (int mt = 0; mt < 2; mt++)
#pragma unroll
                for (int nt = 0; nt < 8; nt++)
                    mma_f16(acc[mt][nt], a[mt], b[nt]);
        }

        // fold tile every 4 chunks: branch-free int-packed top-2
        if ((cc & 3) == 3) {
            const int t = cc >> 2;
            const float2* nsp = (const float2*)(Ns + (t & 1) * NTILE);
#pragma unroll
            for (int nt = 0; nt < 8; nt++) {
                float2 nn = nsp[nw * 32 + nt * 4 + tig];
                const int c0 = t * NTILE + nw * 64 + nt * 8 + 2 * tig;
#pragma unroll
                for (int mt = 0; mt < 2; mt++) {
#pragma unroll
                    for (int r = 0; r < 4; r++) {
                        float nrm = (r & 1) ? nn.y : nn.x;
                        float sv = fmaf(nrm, -0.5f, acc[mt][nt][r]);
                        int key = __float2int_rn(sv * 128.0f) * 16384 +
                                  (c0 + (r & 1));
                        const int sl = mt * 2 + (r >> 1);
                        int nv1 = max(v1[sl], key);
                        v2[sl] = max(v2[sl], min(v1[sl], key));
                        v1[sl] = nv1;
                        acc[mt][nt][r] = 0.f;
                    }
                }
            }
        }
    }

    // ---- cross-thread top-2 reduce (16 contributors per pixel) ----
    __syncthreads();
    int2* red = (int2*)dsm;       // [128 px][16]
#pragma unroll
    for (int s = 0; s < 4; s++) {
        int pxl = mw * 32 + (s >> 1) * 16 + (s & 1) * 8 + g;
        red[pxl * 16 + nw * 4 + tig] = make_int2(v1[s], v2[s]);
    }
    __syncthreads();
    if (tid < PX_CTA) {
        int bv1 = INT_MIN, bv2 = INT_MIN;
#pragma unroll
        for (int c = 0; c < 16; c++) {
            int2 e = red[tid * 16 + c];
            int nv1 = max(bv1, e.x);
            bv2 = max(bv2, min(bv1, e.x));
            bv1 = nv1;
            nv1 = max(bv1, e.y);
            bv2 = max(bv2, min(bv1, e.y));
            bv1 = nv1;
        }
        s_cand[tid] = make_int2(bv1 & 16383, bv2 & 16383);
    }
    __syncthreads();

    // ---- exact fp32 rescore of the 2 candidates per pixel ----
#pragma unroll 1
    for (int j = 0; j < 8; j++) {
        const int pxl = wid * 8 + j;
        const int px = p0 + pxl;
        const int2 cand = s_cand[pxl];
        const float4* zp = (const float4*)(g_Zte + (size_t)px * DIM);
        const float4* e1 = (const float4*)(emb + (size_t)cand.x * DIM);
        const float4* e2 = (const float4*)(emb + (size_t)cand.y * DIM);
        float d1 = 0.f, d2 = 0.f;
#pragma unroll
        for (int t = 0; t < 2; t++) {
            float4 zv = zp[lane + 32 * t];
            float4 a = e1[lane + 32 * t];
            float4 b = e2[lane + 32 * t];
            d1 += zv.x * a.x + zv.y * a.y + zv.z * a.z + zv.w * a.w;
            d2 += zv.x * b.x + zv.y * b.y + zv.z * b.z + zv.w * b.w;
        }
#pragma unroll
        for (int o = 16; o > 0; o >>= 1) {
            d1 += __shfl_xor_sync(0xffffffffu, d1, o);
            d2 += __shfl_xor_sync(0xffffffffu, d2, o);
        }
        if (lane == 0) {
            float s1 = d1 - 0.5f * g_norm2[cand.x];
            float s2 = d2 - 0.5f * g_norm2[cand.y];
            int best;
            if (s1 > s2) best = cand.x;
            else if (s2 > s1) best = cand.y;
            else best = min(cand.x, cand.y);
            s_sel[pxl] = best;
            out[IDX_OFF + px] = (float)best;
        }
    }
    __syncthreads();

    // ---- gather z_q in NCHW ----
    const int b = p0 >> 10;
    const int hw0 = p0 & (HW - 1);
    for (int i = tid; i < DIM * PX_CTA; i += GT) {
        int d = i >> 7, pxl = i & 127;
        out[((size_t)b * DIM + d) * HW + hw0 + pxl] =
            emb[(size_t)s_sel[pxl] * DIM + d];
    }
    if (blockIdx.x == 0 && tid == 0) out[LOSS_OFF] = 0.f;
}

// ---------------------------------------------------------------------------
extern "C" void kernel_launch(void* const* d_in, const int* in_sizes, int n_in,
                              void* d_out, int out_size) {
    const float* z = (const float*)d_in[0];
    const float* emb = (const float*)d_in[1];
    float* out = (float*)d_out;
    (void)in_sizes; (void)n_in; (void)out_size;

    static bool attr_set = false;
    if (!attr_set) {
        cudaFuncSetAttribute(vq_gemm_kernel,
                             cudaFuncAttributeMaxDynamicSharedMemorySize,
                             DYN_BYTES);
        attr_set = true;
    }

    prep_kernel<<<2560, 256>>>(z, emb);
    vq_gemm_kernel<<<N_PIX / PX_CTA, GT, DYN_BYTES>>>(emb, out);
}